// round 11
// baseline (speedup 1.0000x reference)
#include <cuda_runtime.h>
#include <float.h>

#define Bn 4
#define Nn 16384
#define Sn 4096
#define Cin 256
#define Cout 256

#define SPLITS 4
#define SCHUNK (Sn / SPLITS)   // 1024 candidates per CTA

typedef unsigned long long u64;

__device__ __forceinline__ u64 pack2(float x, float y) {
    u64 r; asm("mov.b64 %0, {%1,%2};" : "=l"(r) : "f"(x), "f"(y)); return r;
}
__device__ __forceinline__ u64 ffma2(u64 a, u64 b, u64 c) {
    u64 d; asm("fma.rn.f32x2 %0, %1, %2, %3;" : "=l"(d) : "l"(a), "l"(b), "l"(c)); return d;
}

// Scratch (device globals -- allocation-free per harness rules)
__device__ float g_G[Bn * Sn * Cout];            // [b][s][o], 16.8 MB
__device__ float g_pd[SPLITS * Bn * Nn * 3];     // partial top-3 rank values
__device__ int   g_pi[SPLITS * Bn * Nn * 3];     // partial top-3 indices

// ---------------------------------------------------------------------------
// K1: G[b][s][o] = sum_c P[b][c][s] * W[o][c] + bias[o]
// 128x128 tile, K-step 8, f32x2 packed FMA, double-buffered. (Measured 58us.)
// BYTE-IDENTICAL to R10.
// ---------------------------------------------------------------------------
__global__ __launch_bounds__(256, 2) void k1_gemm(const float* __restrict__ P,
                                                  const float* __restrict__ W,
                                                  const float* __restrict__ bias) {
    __shared__ float sP[2][8][128];
    __shared__ float sW[2][8][128];

    const int b  = blockIdx.z;
    const int s0 = blockIdx.x * 128;
    const int o0 = blockIdx.y * 128;
    const int tid = threadIdx.x;
    const int txo = tid & 15;
    const int tys = tid >> 4;
    const int obase = txo * 8;
    const int sbase = tys * 8;

    const float* Pb = P + b * Cin * Sn;

    const int lk  = tid >> 5;
    const int ls4 = (tid & 31) * 4;
    const int wo  = tid >> 1;
    const int wk  = (tid & 1) * 4;

    u64 acc[8][4];
#pragma unroll
    for (int i = 0; i < 8; i++)
#pragma unroll
        for (int j = 0; j < 4; j++) acc[i][j] = 0ull;

    float4 pA = *(const float4*)&Pb[lk * Sn + s0 + ls4];
    float4 pW = *(const float4*)&W[(o0 + wo) * Cin + wk];
    *(float4*)&sP[0][lk][ls4] = pA;
    sW[0][wk + 0][wo] = pW.x;
    sW[0][wk + 1][wo] = pW.y;
    sW[0][wk + 2][wo] = pW.z;
    sW[0][wk + 3][wo] = pW.w;
    __syncthreads();

    for (int step = 0; step < 32; step++) {
        const int cur = step & 1;
        const int nxt = cur ^ 1;
        if (step < 31) {
            const int k0 = (step + 1) * 8;
            pA = *(const float4*)&Pb[(k0 + lk) * Sn + s0 + ls4];
            pW = *(const float4*)&W[(o0 + wo) * Cin + k0 + wk];
        }

#pragma unroll
        for (int k = 0; k < 8; k++) {
            const ulonglong2 w01 = *(const ulonglong2*)&sW[cur][k][obase];
            const ulonglong2 w23 = *(const ulonglong2*)&sW[cur][k][obase + 4];
            const float4 a0 = *(const float4*)&sP[cur][k][sbase];
            const float4 a1 = *(const float4*)&sP[cur][k][sbase + 4];
            const u64 ad[8] = {pack2(a0.x, a0.x), pack2(a0.y, a0.y),
                               pack2(a0.z, a0.z), pack2(a0.w, a0.w),
                               pack2(a1.x, a1.x), pack2(a1.y, a1.y),
                               pack2(a1.z, a1.z), pack2(a1.w, a1.w)};
            const u64 wv[4] = {w01.x, w01.y, w23.x, w23.y};
#pragma unroll
            for (int i = 0; i < 8; i++)
#pragma unroll
                for (int j = 0; j < 4; j++)
                    acc[i][j] = ffma2(ad[i], wv[j], acc[i][j]);
        }

        if (step < 31) {
            *(float4*)&sP[nxt][lk][ls4] = pA;
            sW[nxt][wk + 0][wo] = pW.x;
            sW[nxt][wk + 1][wo] = pW.y;
            sW[nxt][wk + 2][wo] = pW.z;
            sW[nxt][wk + 3][wo] = pW.w;
        }
        __syncthreads();
    }

    float* Gb = g_G + b * Sn * Cout;
    const float4 bb0 = *(const float4*)&bias[o0 + obase];
    const float4 bb1 = *(const float4*)&bias[o0 + obase + 4];
#pragma unroll
    for (int i = 0; i < 8; i++) {
        const float2 p0 = *(float2*)&acc[i][0];
        const float2 p1 = *(float2*)&acc[i][1];
        const float2 p2 = *(float2*)&acc[i][2];
        const float2 p3 = *(float2*)&acc[i][3];
        float4 v0, v1;
        v0.x = p0.x + bb0.x; v0.y = p0.y + bb0.y;
        v0.z = p1.x + bb0.z; v0.w = p1.y + bb0.w;
        v1.x = p2.x + bb1.x; v1.y = p2.y + bb1.y;
        v1.z = p3.x + bb1.z; v1.w = p3.y + bb1.w;
        float* row = &Gb[(s0 + sbase + i) * Cout + o0 + obase];
        *(float4*)&row[0] = v0;
        *(float4*)&row[4] = v1;
    }
}

// ---------------------------------------------------------------------------
// K2a: partial 3-NN over one S-chunk. 1 point/thread, 4-candidate groups with
// a single min-gated region; inside the gate the insert is BRANCHLESS
// (3 setp + 10 sel per candidate, sorted d0<=d1<=d2 invariant; strict <
// reproduces sequential-insertion tie-break exactly).
// Grid (Nn/256, SPLITS, Bn) = 1024 CTAs.
// ---------------------------------------------------------------------------
__global__ __launch_bounds__(256) void k2_partial(const float* __restrict__ xyz1,
                                                  const float* __restrict__ xyz2) {
    __shared__ float4 qtab[SCHUNK];   // 16 KB

    const int b   = blockIdx.z;
    const int sp  = blockIdx.y;
    const int n0  = blockIdx.x * 256;
    const int tid = threadIdx.x;
    const int sb  = sp * SCHUNK;

    const float* x2 = xyz2 + b * 3 * Sn;
    for (int s = tid; s < SCHUNK; s += 256) {
        const float x = x2[sb + s];
        const float y = x2[Sn + sb + s];
        const float z = x2[2 * Sn + sb + s];
        qtab[s] = make_float4(-2.f * x, -2.f * y, -2.f * z, x * x + y * y + z * z);
    }
    __syncthreads();

    const int n = n0 + tid;
    const float* x1 = xyz1 + b * 3 * Nn;
    const float px = x1[n];
    const float py = x1[Nn + n];
    const float pz = x1[2 * Nn + n];

    float d0 = FLT_MAX, d1 = FLT_MAX, d2 = FLT_MAX;
    int   i0 = 0, i1 = 0, i2 = 0;

#pragma unroll 2
    for (int s = 0; s < SCHUNK; s += 4) {
        const float4 q0 = qtab[s + 0];
        const float4 q1 = qtab[s + 1];
        const float4 q2 = qtab[s + 2];
        const float4 q3 = qtab[s + 3];
        const float e0 = fmaf(px, q0.x, fmaf(py, q0.y, fmaf(pz, q0.z, q0.w)));
        const float e1 = fmaf(px, q1.x, fmaf(py, q1.y, fmaf(pz, q1.z, q1.w)));
        const float e2 = fmaf(px, q2.x, fmaf(py, q2.y, fmaf(pz, q2.z, q2.w)));
        const float e3 = fmaf(px, q3.x, fmaf(py, q3.y, fmaf(pz, q3.z, q3.w)));
        const float m = fminf(fminf(e0, e1), fminf(e2, e3));
        if (m < d2) {
            const float ee[4] = {e0, e1, e2, e3};
#pragma unroll
            for (int j = 0; j < 4; j++) {
                const float e = ee[j];
                const int  gs = sb + s + j;
                const bool b0 = e < d0;
                const bool b1 = e < d1;
                const bool b2 = e < d2;
                const float nd2 = b1 ? d1 : (b2 ? e : d2);
                const int   ni2 = b1 ? i1 : (b2 ? gs : i2);
                const float nd1 = b0 ? d0 : (b1 ? e : d1);
                const int   ni1 = b0 ? i0 : (b1 ? gs : i1);
                d0 = b0 ? e : d0;
                i0 = b0 ? gs : i0;
                d1 = nd1; i1 = ni1;
                d2 = nd2; i2 = ni2;
            }
        }
    }

    const int base = ((sp * Bn + b) * Nn + n) * 3;
    g_pd[base + 0] = d0;
    g_pd[base + 1] = d1;
    g_pd[base + 2] = d2;
    g_pi[base + 0] = i0;
    g_pi[base + 1] = i1;
    g_pi[base + 2] = i2;
}

// ---------------------------------------------------------------------------
// K3: fused merge + gather + weighted sum + transpose-write.
// BYTE-IDENTICAL to R10.
// ---------------------------------------------------------------------------
#define ACC_PITCH 261

__global__ __launch_bounds__(256) void k3_gather(const float* __restrict__ xyz1,
                                                 float* __restrict__ out) {
    extern __shared__ unsigned char smem_raw[];
    float* acc = (float*)smem_raw;            // [64][ACC_PITCH]
    __shared__ float sw[64 * 3];
    __shared__ int   si[64 * 3];

    const int b   = blockIdx.y;
    const int n0  = blockIdx.x * 64;
    const int tid = threadIdx.x;

    // merge phase: one thread per point
    if (tid < 64) {
        const int n = n0 + tid;
        float d0 = FLT_MAX, d1 = FLT_MAX, d2 = FLT_MAX;
        int   i0 = 0, i1 = 0, i2 = 0;
#pragma unroll
        for (int sp = 0; sp < SPLITS; sp++) {
            const int base = ((sp * Bn + b) * Nn + n) * 3;
#pragma unroll
            for (int r = 0; r < 3; r++) {
                const float e  = g_pd[base + r];
                const int   id = g_pi[base + r];
                if (e < d2) {
                    if (e < d0)      { d2 = d1; i2 = i1; d1 = d0; i1 = i0; d0 = e; i0 = id; }
                    else if (e < d1) { d2 = d1; i2 = i1; d1 = e;  i1 = id; }
                    else             { d2 = e;  i2 = id; }
                }
            }
        }
        const float* x1 = xyz1 + b * 3 * Nn;
        const float px = x1[n], py = x1[Nn + n], pz = x1[2 * Nn + n];
        const float pn = px * px + py * py + pz * pz;
        const float r0 = 1.f / (d0 + pn + 1e-8f);
        const float r1 = 1.f / (d1 + pn + 1e-8f);
        const float r2 = 1.f / (d2 + pn + 1e-8f);
        const float inv = 1.f / (r0 + r1 + r2);
        sw[3 * tid + 0] = r0 * inv;
        sw[3 * tid + 1] = r1 * inv;
        sw[3 * tid + 2] = r2 * inv;
        si[3 * tid + 0] = i0;
        si[3 * tid + 1] = i1;
        si[3 * tid + 2] = i2;
    }
    __syncthreads();

    const float* Gb = g_G + b * Sn * Cout;
    const int grp = tid >> 6;        // 0..3
    const int lane = tid & 63;       // 0..63 -> channels 4*lane..4*lane+3

#pragma unroll 2
    for (int p = grp; p < 64; p += 4) {
        const float w0 = sw[3 * p + 0];
        const float w1 = sw[3 * p + 1];
        const float w2 = sw[3 * p + 2];
        const int   j0 = si[3 * p + 0];
        const int   j1 = si[3 * p + 1];
        const int   j2 = si[3 * p + 2];
        const float4 a0 = *((const float4*)(Gb + j0 * Cout) + lane);
        const float4 a1 = *((const float4*)(Gb + j1 * Cout) + lane);
        const float4 a2 = *((const float4*)(Gb + j2 * Cout) + lane);
        float4 v;
        v.x = fmaf(w2, a2.x, fmaf(w1, a1.x, w0 * a0.x));
        v.y = fmaf(w2, a2.y, fmaf(w1, a1.y, w0 * a0.y));
        v.z = fmaf(w2, a2.z, fmaf(w1, a1.z, w0 * a0.z));
        v.w = fmaf(w2, a2.w, fmaf(w1, a1.w, w0 * a0.w));
        float* d = &acc[p * ACC_PITCH + 4 * lane];
        d[0] = v.x; d[1] = v.y; d[2] = v.z; d[3] = v.w;
    }
    __syncthreads();

    float* ob = out + b * Cout * Nn;
    for (int idx = tid; idx < 256 * 16; idx += 256) {
        const int c = idx >> 4;
        const int g = idx & 15;
        float4 v;
        v.x = acc[(4 * g + 0) * ACC_PITCH + c];
        v.y = acc[(4 * g + 1) * ACC_PITCH + c];
        v.z = acc[(4 * g + 2) * ACC_PITCH + c];
        v.w = acc[(4 * g + 3) * ACC_PITCH + c];
        *(float4*)&ob[c * Nn + n0 + 4 * g] = v;
    }
}

// ---------------------------------------------------------------------------
extern "C" void kernel_launch(void* const* d_in, const int* in_sizes, int n_in,
                              void* d_out, int out_size) {
    const float* xyz1 = (const float*)d_in[0];   // [B,3,N]
    const float* xyz2 = (const float*)d_in[1];   // [B,3,S]
    const float* P    = (const float*)d_in[2];   // [B,Cin,S]
    const float* W    = (const float*)d_in[3];   // [Cout,Cin]
    const float* bias = (const float*)d_in[4];   // [Cout]
    float* out = (float*)d_out;                  // [B,Cout,N]

    cudaFuncSetAttribute(k3_gather, cudaFuncAttributeMaxDynamicSharedMemorySize,
                         64 * ACC_PITCH * (int)sizeof(float));

    k1_gemm<<<dim3(Sn / 128, Cout / 128, Bn), 256>>>(P, W, bias);
    k2_partial<<<dim3(Nn / 256, SPLITS, Bn), 256>>>(xyz1, xyz2);
    k3_gather<<<dim3(Nn / 64, Bn), 256, 64 * ACC_PITCH * sizeof(float)>>>(xyz1, out);
}

// round 12
// speedup vs baseline: 1.1714x; 1.1714x over previous
#include <cuda_runtime.h>
#include <float.h>

#define Bn 4
#define Nn 16384
#define Sn 4096
#define Cin 256
#define Cout 256

#define SPLITS 4
#define SCHUNK (Sn / SPLITS)   // 1024 candidates per CTA
#define NPAIR  (SCHUNK / 2)    // 512 candidate pairs

typedef unsigned long long u64;

__device__ __forceinline__ u64 pack2(float x, float y) {
    u64 r; asm("mov.b64 %0, {%1,%2};" : "=l"(r) : "f"(x), "f"(y)); return r;
}
__device__ __forceinline__ void unpack2(u64 v, float& x, float& y) {
    asm("mov.b64 {%0,%1}, %2;" : "=f"(x), "=f"(y) : "l"(v));
}
__device__ __forceinline__ u64 ffma2(u64 a, u64 b, u64 c) {
    u64 d; asm("fma.rn.f32x2 %0, %1, %2, %3;" : "=l"(d) : "l"(a), "l"(b), "l"(c)); return d;
}

// Scratch (device globals -- allocation-free per harness rules)
__device__ float g_G[Bn * Sn * Cout];            // [b][s][o], 16.8 MB
__device__ float g_pd[SPLITS * Bn * Nn * 3];     // partial top-3 rank values
__device__ int   g_pi[SPLITS * Bn * Nn * 3];     // partial top-3 indices

// ---------------------------------------------------------------------------
// K1: G[b][s][o] = sum_c P[b][c][s] * W[o][c] + bias[o]
// 128x128 tile, K-step 8, f32x2 packed FMA, double-buffered. (Measured 58us.)
// BYTE-IDENTICAL to R10.
// ---------------------------------------------------------------------------
__global__ __launch_bounds__(256, 2) void k1_gemm(const float* __restrict__ P,
                                                  const float* __restrict__ W,
                                                  const float* __restrict__ bias) {
    __shared__ float sP[2][8][128];
    __shared__ float sW[2][8][128];

    const int b  = blockIdx.z;
    const int s0 = blockIdx.x * 128;
    const int o0 = blockIdx.y * 128;
    const int tid = threadIdx.x;
    const int txo = tid & 15;
    const int tys = tid >> 4;
    const int obase = txo * 8;
    const int sbase = tys * 8;

    const float* Pb = P + b * Cin * Sn;

    const int lk  = tid >> 5;
    const int ls4 = (tid & 31) * 4;
    const int wo  = tid >> 1;
    const int wk  = (tid & 1) * 4;

    u64 acc[8][4];
#pragma unroll
    for (int i = 0; i < 8; i++)
#pragma unroll
        for (int j = 0; j < 4; j++) acc[i][j] = 0ull;

    float4 pA = *(const float4*)&Pb[lk * Sn + s0 + ls4];
    float4 pW = *(const float4*)&W[(o0 + wo) * Cin + wk];
    *(float4*)&sP[0][lk][ls4] = pA;
    sW[0][wk + 0][wo] = pW.x;
    sW[0][wk + 1][wo] = pW.y;
    sW[0][wk + 2][wo] = pW.z;
    sW[0][wk + 3][wo] = pW.w;
    __syncthreads();

    for (int step = 0; step < 32; step++) {
        const int cur = step & 1;
        const int nxt = cur ^ 1;
        if (step < 31) {
            const int k0 = (step + 1) * 8;
            pA = *(const float4*)&Pb[(k0 + lk) * Sn + s0 + ls4];
            pW = *(const float4*)&W[(o0 + wo) * Cin + k0 + wk];
        }

#pragma unroll
        for (int k = 0; k < 8; k++) {
            const ulonglong2 w01 = *(const ulonglong2*)&sW[cur][k][obase];
            const ulonglong2 w23 = *(const ulonglong2*)&sW[cur][k][obase + 4];
            const float4 a0 = *(const float4*)&sP[cur][k][sbase];
            const float4 a1 = *(const float4*)&sP[cur][k][sbase + 4];
            const u64 ad[8] = {pack2(a0.x, a0.x), pack2(a0.y, a0.y),
                               pack2(a0.z, a0.z), pack2(a0.w, a0.w),
                               pack2(a1.x, a1.x), pack2(a1.y, a1.y),
                               pack2(a1.z, a1.z), pack2(a1.w, a1.w)};
            const u64 wv[4] = {w01.x, w01.y, w23.x, w23.y};
#pragma unroll
            for (int i = 0; i < 8; i++)
#pragma unroll
                for (int j = 0; j < 4; j++)
                    acc[i][j] = ffma2(ad[i], wv[j], acc[i][j]);
        }

        if (step < 31) {
            *(float4*)&sP[nxt][lk][ls4] = pA;
            sW[nxt][wk + 0][wo] = pW.x;
            sW[nxt][wk + 1][wo] = pW.y;
            sW[nxt][wk + 2][wo] = pW.z;
            sW[nxt][wk + 3][wo] = pW.w;
        }
        __syncthreads();
    }

    float* Gb = g_G + b * Sn * Cout;
    const float4 bb0 = *(const float4*)&bias[o0 + obase];
    const float4 bb1 = *(const float4*)&bias[o0 + obase + 4];
#pragma unroll
    for (int i = 0; i < 8; i++) {
        const float2 p0 = *(float2*)&acc[i][0];
        const float2 p1 = *(float2*)&acc[i][1];
        const float2 p2 = *(float2*)&acc[i][2];
        const float2 p3 = *(float2*)&acc[i][3];
        float4 v0, v1;
        v0.x = p0.x + bb0.x; v0.y = p0.y + bb0.y;
        v0.z = p1.x + bb0.z; v0.w = p1.y + bb0.w;
        v1.x = p2.x + bb1.x; v1.y = p2.y + bb1.y;
        v1.z = p3.x + bb1.z; v1.w = p3.y + bb1.w;
        float* row = &Gb[(s0 + sbase + i) * Cout + o0 + obase];
        *(float4*)&row[0] = v0;
        *(float4*)&row[4] = v1;
    }
}

// ---------------------------------------------------------------------------
// K2a: partial 3-NN over one S-chunk. 1 point/thread.
// Table stores candidate PAIRS ({x0,x1},{y0,y1},{z0,z1},{w0,w1}) so one
// ffma2 chain scores 2 candidates (fma.rn.f32x2 == two rn-FMAs, identical
// numerics). Gate + nested insert identical to R10 (best measured).
// Grid (Nn/256, SPLITS, Bn) = 1024 CTAs, 16 KB table.
// ---------------------------------------------------------------------------
struct QP { ulonglong2 xy; ulonglong2 zw; };   // xy={xx,yy}, zw={zz,ww}; 32B

__global__ __launch_bounds__(256) void k2_partial(const float* __restrict__ xyz1,
                                                  const float* __restrict__ xyz2) {
    __shared__ QP qtab[NPAIR];   // 16 KB

    const int b   = blockIdx.z;
    const int sp  = blockIdx.y;
    const int n0  = blockIdx.x * 256;
    const int tid = threadIdx.x;
    const int sb  = sp * SCHUNK;

    const float* x2 = xyz2 + b * 3 * Sn;
    for (int p = tid; p < NPAIR; p += 256) {
        const float2 x01 = *(const float2*)&x2[sb + 2 * p];
        const float2 y01 = *(const float2*)&x2[Sn + sb + 2 * p];
        const float2 z01 = *(const float2*)&x2[2 * Sn + sb + 2 * p];
        QP q;
        q.xy.x = pack2(-2.f * x01.x, -2.f * x01.y);
        q.xy.y = pack2(-2.f * y01.x, -2.f * y01.y);
        q.zw.x = pack2(-2.f * z01.x, -2.f * z01.y);
        q.zw.y = pack2(x01.x * x01.x + y01.x * y01.x + z01.x * z01.x,
                       x01.y * x01.y + y01.y * y01.y + z01.y * z01.y);
        qtab[p] = q;
    }
    __syncthreads();

    const int n = n0 + tid;
    const float* x1 = xyz1 + b * 3 * Nn;
    const float px = x1[n];
    const float py = x1[Nn + n];
    const float pz = x1[2 * Nn + n];
    const u64 pxx = pack2(px, px);
    const u64 pyy = pack2(py, py);
    const u64 pzz = pack2(pz, pz);

    float d0 = FLT_MAX, d1 = FLT_MAX, d2 = FLT_MAX;
    int   i0 = 0, i1 = 0, i2 = 0;

#pragma unroll 2
    for (int g = 0; g < NPAIR; g += 2) {   // 2 pairs = 4 candidates per group
        const ulonglong2 Axy = qtab[g].xy;
        const ulonglong2 Azw = qtab[g].zw;
        const ulonglong2 Bxy = qtab[g + 1].xy;
        const ulonglong2 Bzw = qtab[g + 1].zw;
        u64 eA = ffma2(pzz, Azw.x, Azw.y);
        u64 eB = ffma2(pzz, Bzw.x, Bzw.y);
        eA = ffma2(pyy, Axy.y, eA);
        eB = ffma2(pyy, Bxy.y, eB);
        eA = ffma2(pxx, Axy.x, eA);
        eB = ffma2(pxx, Bxy.x, eB);
        float e0, e1, e2, e3;
        unpack2(eA, e0, e1);
        unpack2(eB, e2, e3);
        const float m = fminf(fminf(e0, e1), fminf(e2, e3));
        if (m < d2) {
            const float ee[4] = {e0, e1, e2, e3};
#pragma unroll
            for (int j = 0; j < 4; j++) {
                const float e = ee[j];
                if (e < d2) {
                    const int gs = sb + 2 * g + j;
                    if (e < d0)      { d2 = d1; i2 = i1; d1 = d0; i1 = i0; d0 = e; i0 = gs; }
                    else if (e < d1) { d2 = d1; i2 = i1; d1 = e;  i1 = gs; }
                    else             { d2 = e;  i2 = gs; }
                }
            }
        }
    }

    const int base = ((sp * Bn + b) * Nn + n) * 3;
    g_pd[base + 0] = d0;
    g_pd[base + 1] = d1;
    g_pd[base + 2] = d2;
    g_pi[base + 0] = i0;
    g_pi[base + 1] = i1;
    g_pi[base + 2] = i2;
}

// ---------------------------------------------------------------------------
// K3: fused merge + gather + weighted sum + transpose-write.
// BYTE-IDENTICAL to R10.
// ---------------------------------------------------------------------------
#define ACC_PITCH 261

__global__ __launch_bounds__(256) void k3_gather(const float* __restrict__ xyz1,
                                                 float* __restrict__ out) {
    extern __shared__ unsigned char smem_raw[];
    float* acc = (float*)smem_raw;            // [64][ACC_PITCH]
    __shared__ float sw[64 * 3];
    __shared__ int   si[64 * 3];

    const int b   = blockIdx.y;
    const int n0  = blockIdx.x * 64;
    const int tid = threadIdx.x;

    // merge phase: one thread per point
    if (tid < 64) {
        const int n = n0 + tid;
        float d0 = FLT_MAX, d1 = FLT_MAX, d2 = FLT_MAX;
        int   i0 = 0, i1 = 0, i2 = 0;
#pragma unroll
        for (int sp = 0; sp < SPLITS; sp++) {
            const int base = ((sp * Bn + b) * Nn + n) * 3;
#pragma unroll
            for (int r = 0; r < 3; r++) {
                const float e  = g_pd[base + r];
                const int   id = g_pi[base + r];
                if (e < d2) {
                    if (e < d0)      { d2 = d1; i2 = i1; d1 = d0; i1 = i0; d0 = e; i0 = id; }
                    else if (e < d1) { d2 = d1; i2 = i1; d1 = e;  i1 = id; }
                    else             { d2 = e;  i2 = id; }
                }
            }
        }
        const float* x1 = xyz1 + b * 3 * Nn;
        const float px = x1[n], py = x1[Nn + n], pz = x1[2 * Nn + n];
        const float pn = px * px + py * py + pz * pz;
        const float r0 = 1.f / (d0 + pn + 1e-8f);
        const float r1 = 1.f / (d1 + pn + 1e-8f);
        const float r2 = 1.f / (d2 + pn + 1e-8f);
        const float inv = 1.f / (r0 + r1 + r2);
        sw[3 * tid + 0] = r0 * inv;
        sw[3 * tid + 1] = r1 * inv;
        sw[3 * tid + 2] = r2 * inv;
        si[3 * tid + 0] = i0;
        si[3 * tid + 1] = i1;
        si[3 * tid + 2] = i2;
    }
    __syncthreads();

    const float* Gb = g_G + b * Sn * Cout;
    const int grp = tid >> 6;        // 0..3
    const int lane = tid & 63;       // 0..63 -> channels 4*lane..4*lane+3

#pragma unroll 2
    for (int p = grp; p < 64; p += 4) {
        const float w0 = sw[3 * p + 0];
        const float w1 = sw[3 * p + 1];
        const float w2 = sw[3 * p + 2];
        const int   j0 = si[3 * p + 0];
        const int   j1 = si[3 * p + 1];
        const int   j2 = si[3 * p + 2];
        const float4 a0 = *((const float4*)(Gb + j0 * Cout) + lane);
        const float4 a1 = *((const float4*)(Gb + j1 * Cout) + lane);
        const float4 a2 = *((const float4*)(Gb + j2 * Cout) + lane);
        float4 v;
        v.x = fmaf(w2, a2.x, fmaf(w1, a1.x, w0 * a0.x));
        v.y = fmaf(w2, a2.y, fmaf(w1, a1.y, w0 * a0.y));
        v.z = fmaf(w2, a2.z, fmaf(w1, a1.z, w0 * a0.z));
        v.w = fmaf(w2, a2.w, fmaf(w1, a1.w, w0 * a0.w));
        float* d = &acc[p * ACC_PITCH + 4 * lane];
        d[0] = v.x; d[1] = v.y; d[2] = v.z; d[3] = v.w;
    }
    __syncthreads();

    float* ob = out + b * Cout * Nn;
    for (int idx = tid; idx < 256 * 16; idx += 256) {
        const int c = idx >> 4;
        const int g = idx & 15;
        float4 v;
        v.x = acc[(4 * g + 0) * ACC_PITCH + c];
        v.y = acc[(4 * g + 1) * ACC_PITCH + c];
        v.z = acc[(4 * g + 2) * ACC_PITCH + c];
        v.w = acc[(4 * g + 3) * ACC_PITCH + c];
        *(float4*)&ob[c * Nn + n0 + 4 * g] = v;
    }
}

// ---------------------------------------------------------------------------
extern "C" void kernel_launch(void* const* d_in, const int* in_sizes, int n_in,
                              void* d_out, int out_size) {
    const float* xyz1 = (const float*)d_in[0];   // [B,3,N]
    const float* xyz2 = (const float*)d_in[1];   // [B,3,S]
    const float* P    = (const float*)d_in[2];   // [B,Cin,S]
    const float* W    = (const float*)d_in[3];   // [Cout,Cin]
    const float* bias = (const float*)d_in[4];   // [Cout]
    float* out = (float*)d_out;                  // [B,Cout,N]

    cudaFuncSetAttribute(k3_gather, cudaFuncAttributeMaxDynamicSharedMemorySize,
                         64 * ACC_PITCH * (int)sizeof(float));

    k1_gemm<<<dim3(Sn / 128, Cout / 128, Bn), 256>>>(P, W, bias);
    k2_partial<<<dim3(Nn / 256, SPLITS, Bn), 256>>>(xyz1, xyz2);
    k3_gather<<<dim3(Nn / 64, Bn), 256, 64 * ACC_PITCH * sizeof(float)>>>(xyz1, out);
}

// round 13
// speedup vs baseline: 1.2291x; 1.0493x over previous
#include <cuda_runtime.h>
#include <float.h>

#define Bn 4
#define Nn 16384
#define Sn 4096
#define Cin 256
#define Cout 256

#define SPLITS 2
#define SCHUNK (Sn / SPLITS)   // 2048 candidates per CTA
#define NPAIR  (SCHUNK / 2)    // 1024 candidate pairs (32 KB table)

typedef unsigned long long u64;

__device__ __forceinline__ u64 pack2(float x, float y) {
    u64 r; asm("mov.b64 %0, {%1,%2};" : "=l"(r) : "f"(x), "f"(y)); return r;
}
__device__ __forceinline__ void unpack2(u64 v, float& x, float& y) {
    asm("mov.b64 {%0,%1}, %2;" : "=f"(x), "=f"(y) : "l"(v));
}
__device__ __forceinline__ u64 ffma2(u64 a, u64 b, u64 c) {
    u64 d; asm("fma.rn.f32x2 %0, %1, %2, %3;" : "=l"(d) : "l"(a), "l"(b), "l"(c)); return d;
}

// Scratch (device globals -- allocation-free per harness rules)
__device__ float g_G[Bn * Sn * Cout];            // [b][s][o], 16.8 MB
__device__ float g_pd[SPLITS * Bn * Nn * 3];     // partial top-3 rank values
__device__ int   g_pi[SPLITS * Bn * Nn * 3];     // partial top-3 indices

// ---------------------------------------------------------------------------
// K1: G[b][s][o] = sum_c P[b][c][s] * W[o][c] + bias[o]
// 128x128 tile, K-step 8, f32x2 packed FMA, double-buffered. (Measured 58us.)
// BYTE-IDENTICAL to R12.
// ---------------------------------------------------------------------------
__global__ __launch_bounds__(256, 2) void k1_gemm(const float* __restrict__ P,
                                                  const float* __restrict__ W,
                                                  const float* __restrict__ bias) {
    __shared__ float sP[2][8][128];
    __shared__ float sW[2][8][128];

    const int b  = blockIdx.z;
    const int s0 = blockIdx.x * 128;
    const int o0 = blockIdx.y * 128;
    const int tid = threadIdx.x;
    const int txo = tid & 15;
    const int tys = tid >> 4;
    const int obase = txo * 8;
    const int sbase = tys * 8;

    const float* Pb = P + b * Cin * Sn;

    const int lk  = tid >> 5;
    const int ls4 = (tid & 31) * 4;
    const int wo  = tid >> 1;
    const int wk  = (tid & 1) * 4;

    u64 acc[8][4];
#pragma unroll
    for (int i = 0; i < 8; i++)
#pragma unroll
        for (int j = 0; j < 4; j++) acc[i][j] = 0ull;

    float4 pA = *(const float4*)&Pb[lk * Sn + s0 + ls4];
    float4 pW = *(const float4*)&W[(o0 + wo) * Cin + wk];
    *(float4*)&sP[0][lk][ls4] = pA;
    sW[0][wk + 0][wo] = pW.x;
    sW[0][wk + 1][wo] = pW.y;
    sW[0][wk + 2][wo] = pW.z;
    sW[0][wk + 3][wo] = pW.w;
    __syncthreads();

    for (int step = 0; step < 32; step++) {
        const int cur = step & 1;
        const int nxt = cur ^ 1;
        if (step < 31) {
            const int k0 = (step + 1) * 8;
            pA = *(const float4*)&Pb[(k0 + lk) * Sn + s0 + ls4];
            pW = *(const float4*)&W[(o0 + wo) * Cin + k0 + wk];
        }

#pragma unroll
        for (int k = 0; k < 8; k++) {
            const ulonglong2 w01 = *(const ulonglong2*)&sW[cur][k][obase];
            const ulonglong2 w23 = *(const ulonglong2*)&sW[cur][k][obase + 4];
            const float4 a0 = *(const float4*)&sP[cur][k][sbase];
            const float4 a1 = *(const float4*)&sP[cur][k][sbase + 4];
            const u64 ad[8] = {pack2(a0.x, a0.x), pack2(a0.y, a0.y),
                               pack2(a0.z, a0.z), pack2(a0.w, a0.w),
                               pack2(a1.x, a1.x), pack2(a1.y, a1.y),
                               pack2(a1.z, a1.z), pack2(a1.w, a1.w)};
            const u64 wv[4] = {w01.x, w01.y, w23.x, w23.y};
#pragma unroll
            for (int i = 0; i < 8; i++)
#pragma unroll
                for (int j = 0; j < 4; j++)
                    acc[i][j] = ffma2(ad[i], wv[j], acc[i][j]);
        }

        if (step < 31) {
            *(float4*)&sP[nxt][lk][ls4] = pA;
            sW[nxt][wk + 0][wo] = pW.x;
            sW[nxt][wk + 1][wo] = pW.y;
            sW[nxt][wk + 2][wo] = pW.z;
            sW[nxt][wk + 3][wo] = pW.w;
        }
        __syncthreads();
    }

    float* Gb = g_G + b * Sn * Cout;
    const float4 bb0 = *(const float4*)&bias[o0 + obase];
    const float4 bb1 = *(const float4*)&bias[o0 + obase + 4];
#pragma unroll
    for (int i = 0; i < 8; i++) {
        const float2 p0 = *(float2*)&acc[i][0];
        const float2 p1 = *(float2*)&acc[i][1];
        const float2 p2 = *(float2*)&acc[i][2];
        const float2 p3 = *(float2*)&acc[i][3];
        float4 v0, v1;
        v0.x = p0.x + bb0.x; v0.y = p0.y + bb0.y;
        v0.z = p1.x + bb0.z; v0.w = p1.y + bb0.w;
        v1.x = p2.x + bb1.x; v1.y = p2.y + bb1.y;
        v1.z = p3.x + bb1.z; v1.w = p3.y + bb1.w;
        float* row = &Gb[(s0 + sbase + i) * Cout + o0 + obase];
        *(float4*)&row[0] = v0;
        *(float4*)&row[4] = v1;
    }
}

// ---------------------------------------------------------------------------
// K2a: partial 3-NN over one S-chunk. 1 point/thread, candidate-pair f32x2
// packing, min-gated 4-candidate groups, nested insert (R10/R12 proven).
// SPLITS=2: grid (Nn/256, 2, Bn) = 512 CTAs, 32 KB table -> ~28 warps/SM,
// 33% fewer total warp-coherent taken-groups than SPLITS=4.
// ---------------------------------------------------------------------------
struct QP { ulonglong2 xy; ulonglong2 zw; };   // xy={xx,yy}, zw={zz,ww}; 32B

__global__ __launch_bounds__(256) void k2_partial(const float* __restrict__ xyz1,
                                                  const float* __restrict__ xyz2) {
    __shared__ QP qtab[NPAIR];   // 32 KB

    const int b   = blockIdx.z;
    const int sp  = blockIdx.y;
    const int n0  = blockIdx.x * 256;
    const int tid = threadIdx.x;
    const int sb  = sp * SCHUNK;

    const float* x2 = xyz2 + b * 3 * Sn;
    for (int p = tid; p < NPAIR; p += 256) {
        const float2 x01 = *(const float2*)&x2[sb + 2 * p];
        const float2 y01 = *(const float2*)&x2[Sn + sb + 2 * p];
        const float2 z01 = *(const float2*)&x2[2 * Sn + sb + 2 * p];
        QP q;
        q.xy.x = pack2(-2.f * x01.x, -2.f * x01.y);
        q.xy.y = pack2(-2.f * y01.x, -2.f * y01.y);
        q.zw.x = pack2(-2.f * z01.x, -2.f * z01.y);
        q.zw.y = pack2(x01.x * x01.x + y01.x * y01.x + z01.x * z01.x,
                       x01.y * x01.y + y01.y * y01.y + z01.y * z01.y);
        qtab[p] = q;
    }
    __syncthreads();

    const int n = n0 + tid;
    const float* x1 = xyz1 + b * 3 * Nn;
    const float px = x1[n];
    const float py = x1[Nn + n];
    const float pz = x1[2 * Nn + n];
    const u64 pxx = pack2(px, px);
    const u64 pyy = pack2(py, py);
    const u64 pzz = pack2(pz, pz);

    float d0 = FLT_MAX, d1 = FLT_MAX, d2 = FLT_MAX;
    int   i0 = 0, i1 = 0, i2 = 0;

#pragma unroll 2
    for (int g = 0; g < NPAIR; g += 2) {   // 2 pairs = 4 candidates per group
        const ulonglong2 Axy = qtab[g].xy;
        const ulonglong2 Azw = qtab[g].zw;
        const ulonglong2 Bxy = qtab[g + 1].xy;
        const ulonglong2 Bzw = qtab[g + 1].zw;
        u64 eA = ffma2(pzz, Azw.x, Azw.y);
        u64 eB = ffma2(pzz, Bzw.x, Bzw.y);
        eA = ffma2(pyy, Axy.y, eA);
        eB = ffma2(pyy, Bxy.y, eB);
        eA = ffma2(pxx, Axy.x, eA);
        eB = ffma2(pxx, Bxy.x, eB);
        float e0, e1, e2, e3;
        unpack2(eA, e0, e1);
        unpack2(eB, e2, e3);
        const float m = fminf(fminf(e0, e1), fminf(e2, e3));
        if (m < d2) {
            const float ee[4] = {e0, e1, e2, e3};
#pragma unroll
            for (int j = 0; j < 4; j++) {
                const float e = ee[j];
                if (e < d2) {
                    const int gs = sb + 2 * g + j;
                    if (e < d0)      { d2 = d1; i2 = i1; d1 = d0; i1 = i0; d0 = e; i0 = gs; }
                    else if (e < d1) { d2 = d1; i2 = i1; d1 = e;  i1 = gs; }
                    else             { d2 = e;  i2 = gs; }
                }
            }
        }
    }

    const int base = ((sp * Bn + b) * Nn + n) * 3;
    g_pd[base + 0] = d0;
    g_pd[base + 1] = d1;
    g_pd[base + 2] = d2;
    g_pi[base + 0] = i0;
    g_pi[base + 1] = i1;
    g_pi[base + 2] = i2;
}

// ---------------------------------------------------------------------------
// K3: fused merge + gather + weighted sum + transpose-write.
// BYTE-IDENTICAL to R12 (merge loop adapts via SPLITS macro).
// ---------------------------------------------------------------------------
#define ACC_PITCH 261

__global__ __launch_bounds__(256) void k3_gather(const float* __restrict__ xyz1,
                                                 float* __restrict__ out) {
    extern __shared__ unsigned char smem_raw[];
    float* acc = (float*)smem_raw;            // [64][ACC_PITCH]
    __shared__ float sw[64 * 3];
    __shared__ int   si[64 * 3];

    const int b   = blockIdx.y;
    const int n0  = blockIdx.x * 64;
    const int tid = threadIdx.x;

    // merge phase: one thread per point
    if (tid < 64) {
        const int n = n0 + tid;
        float d0 = FLT_MAX, d1 = FLT_MAX, d2 = FLT_MAX;
        int   i0 = 0, i1 = 0, i2 = 0;
#pragma unroll
        for (int sp = 0; sp < SPLITS; sp++) {
            const int base = ((sp * Bn + b) * Nn + n) * 3;
#pragma unroll
            for (int r = 0; r < 3; r++) {
                const float e  = g_pd[base + r];
                const int   id = g_pi[base + r];
                if (e < d2) {
                    if (e < d0)      { d2 = d1; i2 = i1; d1 = d0; i1 = i0; d0 = e; i0 = id; }
                    else if (e < d1) { d2 = d1; i2 = i1; d1 = e;  i1 = id; }
                    else             { d2 = e;  i2 = id; }
                }
            }
        }
        const float* x1 = xyz1 + b * 3 * Nn;
        const float px = x1[n], py = x1[Nn + n], pz = x1[2 * Nn + n];
        const float pn = px * px + py * py + pz * pz;
        const float r0 = 1.f / (d0 + pn + 1e-8f);
        const float r1 = 1.f / (d1 + pn + 1e-8f);
        const float r2 = 1.f / (d2 + pn + 1e-8f);
        const float inv = 1.f / (r0 + r1 + r2);
        sw[3 * tid + 0] = r0 * inv;
        sw[3 * tid + 1] = r1 * inv;
        sw[3 * tid + 2] = r2 * inv;
        si[3 * tid + 0] = i0;
        si[3 * tid + 1] = i1;
        si[3 * tid + 2] = i2;
    }
    __syncthreads();

    const float* Gb = g_G + b * Sn * Cout;
    const int grp = tid >> 6;        // 0..3
    const int lane = tid & 63;       // 0..63 -> channels 4*lane..4*lane+3

#pragma unroll 2
    for (int p = grp; p < 64; p += 4) {
        const float w0 = sw[3 * p + 0];
        const float w1 = sw[3 * p + 1];
        const float w2 = sw[3 * p + 2];
        const int   j0 = si[3 * p + 0];
        const int   j1 = si[3 * p + 1];
        const int   j2 = si[3 * p + 2];
        const float4 a0 = *((const float4*)(Gb + j0 * Cout) + lane);
        const float4 a1 = *((const float4*)(Gb + j1 * Cout) + lane);
        const float4 a2 = *((const float4*)(Gb + j2 * Cout) + lane);
        float4 v;
        v.x = fmaf(w2, a2.x, fmaf(w1, a1.x, w0 * a0.x));
        v.y = fmaf(w2, a2.y, fmaf(w1, a1.y, w0 * a0.y));
        v.z = fmaf(w2, a2.z, fmaf(w1, a1.z, w0 * a0.z));
        v.w = fmaf(w2, a2.w, fmaf(w1, a1.w, w0 * a0.w));
        float* d = &acc[p * ACC_PITCH + 4 * lane];
        d[0] = v.x; d[1] = v.y; d[2] = v.z; d[3] = v.w;
    }
    __syncthreads();

    float* ob = out + b * Cout * Nn;
    for (int idx = tid; idx < 256 * 16; idx += 256) {
        const int c = idx >> 4;
        const int g = idx & 15;
        float4 v;
        v.x = acc[(4 * g + 0) * ACC_PITCH + c];
        v.y = acc[(4 * g + 1) * ACC_PITCH + c];
        v.z = acc[(4 * g + 2) * ACC_PITCH + c];
        v.w = acc[(4 * g + 3) * ACC_PITCH + c];
        *(float4*)&ob[c * Nn + n0 + 4 * g] = v;
    }
}

// ---------------------------------------------------------------------------
extern "C" void kernel_launch(void* const* d_in, const int* in_sizes, int n_in,
                              void* d_out, int out_size) {
    const float* xyz1 = (const float*)d_in[0];   // [B,3,N]
    const float* xyz2 = (const float*)d_in[1];   // [B,3,S]
    const float* P    = (const float*)d_in[2];   // [B,Cin,S]
    const float* W    = (const float*)d_in[3];   // [Cout,Cin]
    const float* bias = (const float*)d_in[4];   // [Cout]
    float* out = (float*)d_out;                  // [B,Cout,N]

    cudaFuncSetAttribute(k3_gather, cudaFuncAttributeMaxDynamicSharedMemorySize,
                         64 * ACC_PITCH * (int)sizeof(float));

    k1_gemm<<<dim3(Sn / 128, Cout / 128, Bn), 256>>>(P, W, bias);
    k2_partial<<<dim3(Nn / 256, SPLITS, Bn), 256>>>(xyz1, xyz2);
    k3_gather<<<dim3(Nn / 64, Bn), 256, 64 * ACC_PITCH * sizeof(float)>>>(xyz1, out);
}